// round 17
// baseline (speedup 1.0000x reference)
#include <cuda_runtime.h>
#include <cuda_fp16.h>
#include <cstdint>

// NearestEmbed: x (64,64,32,32) f32, emb (64,512) f32
// out f32 = [ quantized 4194304 | argmin 65536 (as float) ]
//
// R17: code-partitioned HMMA. Warp w owns codes [32w,32w+32): its B fragments
// live in 32 REGISTERS (built once). A fragments (fp16, pre-scaled by -2)
// are staged in smem per 256-row tile; each warp scans all rows in 16-row
// chunks: 4 LDS.128 feed 16 HMMA (norm-initialized accumulators = scores).
// Per-row top-2 merged across warps in smem (ascending code, strict <).
// Exact fp32 rescue + gather epilogue as in R8 (proven).

#define THREADS 512
#define TILE_M 256
#define GRID 128
#define TILES_PER_CTA 2
#define EMB_D 64
#define EMB_K 512
#define HW 1024
#define MARGIN 0.04f

// smem layout (bytes)
#define SM_EMB    0                        // f32 emb_s[64][512] = 128KB
#define SM_AFRAG  131072                   // uint4 afrag[16 chunk][4 ks][32 lane] = 32KB
#define SM_SCR    163840                   // scratch 48KB: xh (fp16 [256][66]) then top2buf
#define SM_NORMS  212992                   // f32 [512] = 2KB
#define SM_WIN    215040                   // i32 [256]
#define SM_QUEUE  216064                   // i32 [256]
#define SM_QCNT   217088                   // i32
#define SM_XS     217104                   // f32 [16 warps][64] = 4KB (rescue)
#define SM_TOTAL  221200

#define XH_STRIDE 66                       // halves per row (pad: bank-conflict-free)

__device__ __forceinline__ uint32_t packh2(float a, float b) {
    __half2 h = __floats2half2_rn(a, b);
    return *reinterpret_cast<uint32_t*>(&h);
}

__device__ __forceinline__ void hmma16816(float& c0, float& c1, float& c2, float& c3,
                                          uint32_t a0, uint32_t a1, uint32_t a2, uint32_t a3,
                                          uint32_t b0, uint32_t b1) {
    asm volatile("mma.sync.aligned.m16n8k16.row.col.f32.f16.f16.f32 "
                 "{%0,%1,%2,%3}, {%4,%5,%6,%7}, {%8,%9}, {%0,%1,%2,%3};"
                 : "+f"(c0), "+f"(c1), "+f"(c2), "+f"(c3)
                 : "r"(a0), "r"(a1), "r"(a2), "r"(a3), "r"(b0), "r"(b1));
}

// Branch-free top-2 update with a pair of adjacent-code scores (R13/R16-verified).
__device__ __forceinline__ void top2_pair(float s0, float s1, int n0,
                                          float& b1, float& b2, int& k1) {
    float sm = fminf(s0, s1);
    float pm = fmaxf(s0, s1);
    int  km = n0 + ((s1 < s0) ? 1 : 0);
    bool take = (sm < b1);
    float t1 = take ? b1 : b2;
    float t2 = take ? pm : sm;
    b2 = fminf(t1, fminf(b2, t2));
    b1 = take ? sm : b1;
    k1 = take ? km : k1;
}

// lane-merge of top-2 state across xor offsets 1,2 (index-aware ties)
__device__ __forceinline__ void lane_merge(float& b1, float& b2, int& k1) {
    #pragma unroll
    for (int off = 1; off <= 2; off <<= 1) {
        float ob1 = __shfl_xor_sync(0xffffffffu, b1, off);
        int   ok1 = __shfl_xor_sync(0xffffffffu, k1, off);
        float ob2 = __shfl_xor_sync(0xffffffffu, b2, off);
        float nb2 = fminf(fmaxf(b1, ob1), fminf(b2, ob2));
        bool take = (ob1 < b1) || (ob1 == b1 && ok1 < k1);
        b1 = take ? ob1 : b1; k1 = take ? ok1 : k1; b2 = nb2;
    }
}

__global__ __launch_bounds__(THREADS, 1)
void vq_hmma_kernel(const float* __restrict__ x,
                    const float* __restrict__ emb,
                    float* __restrict__ out_q,
                    float* __restrict__ out_idx)
{
    extern __shared__ char smem[];
    float*    emb_s = reinterpret_cast<float*>(smem + SM_EMB);
    uint4*    afrag = reinterpret_cast<uint4*>(smem + SM_AFRAG);
    __half*   xh    = reinterpret_cast<__half*>(smem + SM_SCR);          // staging phase
    float*    t_b1  = reinterpret_cast<float*>(smem + SM_SCR);           // merge phase
    float*    t_b2  = reinterpret_cast<float*>(smem + SM_SCR + 16384);
    int*      t_k   = reinterpret_cast<int*>(smem + SM_SCR + 32768);
    float*    norms = reinterpret_cast<float*>(smem + SM_NORMS);
    int*      winners = reinterpret_cast<int*>(smem + SM_WIN);
    int*      queue   = reinterpret_cast<int*>(smem + SM_QUEUE);
    int*      qcnt    = reinterpret_cast<int*>(smem + SM_QCNT);
    float*    xscr    = reinterpret_cast<float*>(smem + SM_XS);

    const int tid  = threadIdx.x;
    const int warp = tid >> 5;
    const int lane = tid & 31;
    const int gidq = lane & 3;
    const int grp  = lane >> 2;

    // ---- Prologue: emb -> smem, norms, per-warp B fragments in REGISTERS ----
    for (int i = tid; i < EMB_D * EMB_K; i += THREADS) emb_s[i] = emb[i];
    if (tid == 0) *qcnt = 0;
    __syncthreads();

    for (int k = tid; k < EMB_K; k += THREADS) {
        float s = 0.f;
        #pragma unroll
        for (int d = 0; d < EMB_D; d++) {
            float v = emb_s[d * EMB_K + k];
            s = fmaf(v, v, s);
        }
        norms[k] = s;
    }

    // B regs: warp w owns codes [32w, 32w+32) = n-tiles {4w..4w+3}
    uint32_t Breg[4][4][2];   // [local nt][ks][j]
    #pragma unroll
    for (int lnt = 0; lnt < 4; lnt++) {
        int n = (warp * 4 + lnt) * 8 + grp;
        #pragma unroll
        for (int ks = 0; ks < 4; ks++) {
            #pragma unroll
            for (int j = 0; j < 2; j++) {
                int d0 = ks * 16 + 2 * gidq + 8 * j;
                Breg[lnt][ks][j] = packh2(emb_s[d0 * EMB_K + n],
                                          emb_s[(d0 + 1) * EMB_K + n]);
            }
        }
    }
    __syncthreads();

    for (int it = 0; it < TILES_PER_CTA; it++) {
        const int tile = blockIdx.x * TILES_PER_CTA + it;
        const int row_base = tile * TILE_M;
        const int b = row_base >> 10;
        const int hw_base = row_base & (HW - 1);
        const float* xb = x + (size_t)b * (EMB_D * HW) + hw_base;   // x(row,d)=xb[d*HW+row]

        // ---- stage xh = half(-2*x) [256 rows][66 halves] (coalesced reads) ----
        for (int i = tid; i < TILE_M * EMB_D; i += THREADS) {
            int d = i >> 8;            // 0..63
            int r = i & (TILE_M - 1);  // 0..255
            xh[r * XH_STRIDE + d] = __float2half(-2.f * xb[(size_t)d * HW + r]);
        }
        __syncthreads();

        // ---- build A fragments [chunk][ks][lane] (uint4) ----
        for (int e = tid; e < 16 * 4 * 32; e += THREADS) {
            int ln = e & 31;
            int ks = (e >> 5) & 3;
            int ch = e >> 7;
            int g  = ln & 3;
            int gp = ln >> 2;
            int d  = ks * 16 + g * 2;
            int r0 = ch * 16 + gp;
            int r1 = r0 + 8;
            uint32_t v0 = *reinterpret_cast<const uint32_t*>(&xh[r0 * XH_STRIDE + d]);
            uint32_t v1 = *reinterpret_cast<const uint32_t*>(&xh[r1 * XH_STRIDE + d]);
            uint32_t v2 = *reinterpret_cast<const uint32_t*>(&xh[r0 * XH_STRIDE + d + 8]);
            uint32_t v3 = *reinterpret_cast<const uint32_t*>(&xh[r1 * XH_STRIDE + d + 8]);
            afrag[e] = make_uint4(v0, v1, v2, v3);
        }
        __syncthreads();   // xh region now dead -> becomes top2buf

        // ---- mainloop: warp scans all 16 chunks for its 32 codes ----
        const int nbase = warp * 32 + gidq * 2;
        #pragma unroll 1
        for (int ch = 0; ch < 16; ch++) {
            const uint4* af = afrag + ch * 128;
            uint4 q0 = af[lane];
            uint4 q1 = af[32 + lane];
            uint4 q2 = af[64 + lane];
            uint4 q3 = af[96 + lane];

            const float INF = __int_as_float(0x7f800000);
            float b1a = INF, b2a = INF, b1b = INF, b2b = INF;
            int k1a = 0, k1b = 0;

            #pragma unroll
            for (int lnt = 0; lnt < 4; lnt++) {
                const int n0 = nbase + lnt * 8;
                float2 nr = *reinterpret_cast<const float2*>(norms + n0);
                float c0 = nr.x, c1 = nr.y, c2 = nr.x, c3 = nr.y;
                hmma16816(c0, c1, c2, c3, q0.x, q0.y, q0.z, q0.w, Breg[lnt][0][0], Breg[lnt][0][1]);
                hmma16816(c0, c1, c2, c3, q1.x, q1.y, q1.z, q1.w, Breg[lnt][1][0], Breg[lnt][1][1]);
                hmma16816(c0, c1, c2, c3, q2.x, q2.y, q2.z, q2.w, Breg[lnt][2][0], Breg[lnt][2][1]);
                hmma16816(c0, c1, c2, c3, q3.x, q3.y, q3.z, q3.w, Breg[lnt][3][0], Breg[lnt][3][1]);
                top2_pair(c0, c1, n0, b1a, b2a, k1a);
                top2_pair(c2, c3, n0, b1b, b2b, k1b);
            }
            lane_merge(b1a, b2a, k1a);
            lane_merge(b1b, b2b, k1b);

            if (gidq == 0) {
                int r0 = ch * 16 + grp;
                t_b1[r0 * 16 + warp] = b1a;
                t_b2[r0 * 16 + warp] = b2a;
                t_k [r0 * 16 + warp] = k1a;
                int r1 = r0 + 8;
                t_b1[r1 * 16 + warp] = b1b;
                t_b2[r1 * 16 + warp] = b2b;
                t_k [r1 * 16 + warp] = k1b;
            }
        }
        __syncthreads();

        // ---- merge across 16 warps per row (ascending code order) ----
        if (tid < TILE_M) {
            const int row = tid;
            float B1 = __int_as_float(0x7f800000), B2 = B1;
            int K1 = 0;
            #pragma unroll
            for (int w = 0; w < 16; w++) {
                float b1v = t_b1[row * 16 + w];
                float b2v = t_b2[row * 16 + w];
                int   kv  = t_k [row * 16 + w];
                if (b1v < B1) { B2 = fminf(B1, b2v); B1 = b1v; K1 = kv; }
                else          { B2 = fminf(B2, b1v); }
            }
            if (B2 - B1 <= MARGIN) { int qi = atomicAdd(qcnt, 1); queue[qi] = row; }
            else winners[row] = K1;
        }
        __syncthreads();

        // ---- exact fp32 rescan for ambiguous rows (rare) ----
        const int nq = *qcnt;
        for (int i = warp; i < nq; i += 16) {
            int lr = queue[i];
            const float* xg = xb + lr;
            float* xs = xscr + warp * 64;
            xs[lane] = xg[(size_t)lane * HW];
            xs[lane + 32] = xg[(size_t)(lane + 32) * HW];
            __syncwarp();
            float best = __int_as_float(0x7f800000);
            int bk = 0;
            #pragma unroll 1
            for (int j = 0; j < 16; j++) {
                int k = lane + 32 * j;
                float acc = 0.f;
                #pragma unroll 8
                for (int d = 0; d < EMB_D; d++)
                    acc = fmaf(xs[d], emb_s[d * EMB_K + k], acc);
                float sc = fmaf(-2.f, acc, norms[k]);
                if (sc < best) { best = sc; bk = k; }
            }
            #pragma unroll
            for (int off = 16; off >= 1; off >>= 1) {
                float os = __shfl_xor_sync(0xffffffffu, best, off);
                int   ok = __shfl_xor_sync(0xffffffffu, bk, off);
                bool take = (os < best) || (os == best && ok < bk);
                best = take ? os : best;
                bk = take ? ok : bk;
            }
            if (lane == 0) winners[lr] = bk;
            __syncwarp();
        }
        __syncthreads();

        // ---- outputs ----
        float* oq = out_q + (size_t)b * (EMB_D * HW) + hw_base;
        for (int i = tid; i < TILE_M * EMB_D; i += THREADS) {
            int r = i & (TILE_M - 1);
            int d = i >> 8;
            oq[(size_t)d * HW + r] = emb_s[d * EMB_K + winners[r]];
        }
        if (tid < TILE_M) out_idx[row_base + tid] = (float)winners[tid];
        if (tid == 0) *qcnt = 0;
        __syncthreads();
    }
}

extern "C" void kernel_launch(void* const* d_in, const int* in_sizes, int n_in,
                              void* d_out, int out_size)
{
    const float* x   = (const float*)d_in[0];   // 4194304 f32
    const float* emb = (const float*)d_in[1];   // 32768 f32
    float* out_q = (float*)d_out;
    float* out_i = (float*)d_out + (size_t)4194304;

    cudaFuncSetAttribute(vq_hmma_kernel,
                         cudaFuncAttributeMaxDynamicSharedMemorySize, SM_TOTAL);
    vq_hmma_kernel<<<GRID, THREADS, SM_TOTAL>>>(x, emb, out_q, out_i);
}